// round 4
// baseline (speedup 1.0000x reference)
#include <cuda_runtime.h>

#define N_NODES 50000
#define K 16
#define F 128
#define T 16
#define M 8

// Precomputed template statistics (device scratch — no allocation allowed)
__device__ __align__(16) float g_tmean[T * F];
__device__ float g_tsq[T];
__device__ float g_mCt[T];
__device__ float g_mCt2[T];

// One block, 512 threads (16 warps). Warp w owns template w's scalar stats;
// tmean is strided across all threads.
__global__ __launch_bounds__(512) void tmpl_stats_kernel(
    const float* __restrict__ tmpl, const float* __restrict__ tf)
{
    const int tid = threadIdx.x;
    const int w = tid >> 5, lane = tid & 31;

    // tmean[t][f] = mean over m of tf[t][m][f]
    for (int i = tid; i < T * F; i += 512) {
        int t = i >> 7, f = i & (F - 1);
        float s = 0.f;
        #pragma unroll
        for (int m = 0; m < M; m++) s += tf[(t * M + m) * F + f];
        g_tmean[i] = s * (1.0f / M);
    }

    // warp w -> template t = w
    const int t = w;
    float s2 = 0.f;
    for (int e = lane; e < M * F; e += 32) {
        float v = tf[t * M * F + e];
        s2 = fmaf(v, v, s2);
    }
    float v0 = tmpl[t * 64 + lane];
    float v1 = tmpl[t * 64 + lane + 32];
    float sa = v0 + v1;
    float sb = v0 * v0 + v1 * v1;
    #pragma unroll
    for (int off = 16; off; off >>= 1) {
        s2 += __shfl_down_sync(0xffffffffu, s2, off);
        sa += __shfl_down_sync(0xffffffffu, sa, off);
        sb += __shfl_down_sync(0xffffffffu, sb, off);
    }
    if (lane == 0) {
        g_tsq[t]  = s2 * (1.0f / M);       // mean over m of sum_f tf^2
        g_mCt[t]  = sa * (1.0f / 64.0f);
        g_mCt2[t] = sb * (1.0f / 64.0f);
    }
}

// One block (128 threads = 4 warps) per node.
__global__ __launch_bounds__(128) void ltfwg_kernel(
    const float* __restrict__ x, const int* __restrict__ nbr,
    float* __restrict__ out)
{
    __shared__ int   s_nbrs[K];
    __shared__ int   s_non[K * K];
    __shared__ __align__(16) float s_fpart[4][F];
    __shared__ __align__(16) float s_fmean[F];
    __shared__ float s_rs2[4];
    __shared__ float s_rcnt[4];

    const int n = blockIdx.x;
    const int tid = threadIdx.x;
    const int w = tid >> 5, lane = tid & 31;

    if (tid < K) s_nbrs[tid] = nbr[n * K + tid];
    __syncthreads();

    // neighbors-of-neighbors gather: 256 entries, 2 per thread
    const int i1 = tid + 128;
    const int nn0 = nbr[s_nbrs[tid >> 4] * K + (tid & 15)];
    const int nn1 = nbr[s_nbrs[i1 >> 4] * K + (i1 & 15)];

    // feature gather: warp w covers rows {w, w+4, w+8, w+12};
    // each warp-load = one full 512B row (float4 per lane, coalesced)
    float4 acc = make_float4(0.f, 0.f, 0.f, 0.f);
    float s2 = 0.f;
    #pragma unroll
    for (int j = 0; j < 4; j++) {
        const int row = s_nbrs[w + 4 * j];
        float4 v = __ldg((const float4*)(x + row * F) + lane);
        acc.x += v.x; acc.y += v.y; acc.z += v.z; acc.w += v.w;
        s2 = fmaf(v.x, v.x, s2); s2 = fmaf(v.y, v.y, s2);
        s2 = fmaf(v.z, v.z, s2); s2 = fmaf(v.w, v.w, s2);
    }
    ((float4*)s_fpart[w])[lane] = acc;
    s_non[tid] = nn0;
    s_non[i1]  = nn1;
    __syncthreads();

    // per-dim feature mean across the 4 warps' partials
    const float fm = (s_fpart[0][tid] + s_fpart[1][tid] +
                      s_fpart[2][tid] + s_fpart[3][tid]) * (1.0f / K);
    s_fmean[tid] = fm;

    // induced adjacency: C[a,b] = any_c (non[a][c] == nbrs[b]); count ones
    int cnt = 0;
    #pragma unroll
    for (int p = 0; p < 2; p++) {
        const int pp = tid + p * 128;
        const int a = pp >> 4, b = pp & 15;
        const int tgt = s_nbrs[b];
        const int* row = &s_non[a * K];
        bool hit = false;
        #pragma unroll
        for (int c = 0; c < K; c++) hit |= (row[c] == tgt);
        cnt += hit ? 1 : 0;
    }

    // joint block reduction of s2 (for sq) and cnt (for mC)
    float cf = (float)cnt;
    #pragma unroll
    for (int off = 16; off; off >>= 1) {
        s2 += __shfl_down_sync(0xffffffffu, s2, off);
        cf += __shfl_down_sync(0xffffffffu, cf, off);
    }
    if (lane == 0) { s_rs2[w] = s2; s_rcnt[w] = cf; }
    __syncthreads();

    const float sq = (s_rs2[0] + s_rs2[1] + s_rs2[2] + s_rs2[3]) * (1.0f / K);
    const float mC = (s_rcnt[0] + s_rcnt[1] + s_rcnt[2] + s_rcnt[3]) * (1.0f / (K * K));

    // fmean . tmean[t]: template t = tid>>3, dim chunk seg = tid&7 (16 dims each)
    const int t = tid >> 3, seg = tid & 7;
    const float4* fm4 = (const float4*)(s_fmean) + seg * 4;
    const float4* tm4 = (const float4*)(g_tmean + t * F) + seg * 4;
    float d = 0.f;
    #pragma unroll
    for (int j = 0; j < 4; j++) {
        const float4 a4 = fm4[j];
        const float4 b4 = __ldg(tm4 + j);
        d = fmaf(a4.x, b4.x, d); d = fmaf(a4.y, b4.y, d);
        d = fmaf(a4.z, b4.z, d); d = fmaf(a4.w, b4.w, d);
    }
    #pragma unroll
    for (int off = 4; off; off >>= 1)
        d += __shfl_down_sync(0xffffffffu, d, off, 8);

    if (seg == 0) {
        const float feat = sq + g_tsq[t] - 2.0f * d;
        const float st   = mC + g_mCt2[t] - 2.0f * mC * g_mCt[t];
        out[n * T + t] = 0.5f * feat + 0.5f * st;   // ALPHA = 0.5
    }
}

extern "C" void kernel_launch(void* const* d_in, const int* in_sizes, int n_in,
                              void* d_out, int out_size) {
    const float* x    = (const float*)d_in[0];
    const int*   edge = (const int*)  d_in[1];   // [2, N*K] int32
    const float* tmpl = (const float*)d_in[2];   // [T, M, M]
    const float* tf   = (const float*)d_in[3];   // [T, M, F]
    float* out = (float*)d_out;

    const int* nbr = edge + N_NODES * K;         // dst row

    tmpl_stats_kernel<<<1, 512>>>(tmpl, tf);
    ltfwg_kernel<<<N_NODES, 128>>>(x, nbr, out);
}

// round 5
// speedup vs baseline: 1.0305x; 1.0305x over previous
#include <cuda_runtime.h>

#define N_NODES 50000
#define K 16
#define F 128
#define T 16
#define M 8

// Precomputed template statistics (device scratch — no allocation allowed)
__device__ __align__(16) float g_tmean[T * F];
__device__ float g_tsq[T];
__device__ float g_mCt[T];
__device__ float g_mCt2[T];

// One block, 512 threads (16 warps). Warp w owns template w's scalar stats;
// tmean is strided across all threads.
__global__ __launch_bounds__(512) void tmpl_stats_kernel(
    const float* __restrict__ tmpl, const float* __restrict__ tf)
{
    const int tid = threadIdx.x;
    const int w = tid >> 5, lane = tid & 31;

    // tmean[t][f] = mean over m of tf[t][m][f]
    for (int i = tid; i < T * F; i += 512) {
        int t = i >> 7, f = i & (F - 1);
        float s = 0.f;
        #pragma unroll
        for (int m = 0; m < M; m++) s += tf[(t * M + m) * F + f];
        g_tmean[i] = s * (1.0f / M);
    }

    // warp w -> template t = w
    const int t = w;
    float s2 = 0.f;
    for (int e = lane; e < M * F; e += 32) {
        float v = tf[t * M * F + e];
        s2 = fmaf(v, v, s2);
    }
    float v0 = tmpl[t * 64 + lane];
    float v1 = tmpl[t * 64 + lane + 32];
    float sa = v0 + v1;
    float sb = v0 * v0 + v1 * v1;
    #pragma unroll
    for (int off = 16; off; off >>= 1) {
        s2 += __shfl_down_sync(0xffffffffu, s2, off);
        sa += __shfl_down_sync(0xffffffffu, sa, off);
        sb += __shfl_down_sync(0xffffffffu, sb, off);
    }
    if (lane == 0) {
        g_tsq[t]  = s2 * (1.0f / M);       // mean over m of sum_f tf^2
        g_mCt[t]  = sa * (1.0f / 64.0f);
        g_mCt2[t] = sb * (1.0f / 64.0f);
    }
}

// One block (128 threads = 4 warps) per node.
__global__ __launch_bounds__(128) void ltfwg_kernel(
    const float* __restrict__ x, const int* __restrict__ nbr,
    float* __restrict__ out)
{
    __shared__ __align__(16) int s_nbrs[K];
    __shared__ __align__(16) float s_fpart[4][F];
    __shared__ __align__(16) float s_fmean[F];
    __shared__ float s_rs2[4];
    __shared__ float s_rcnt[4];

    const int n = blockIdx.x;
    const int tid = threadIdx.x;
    const int w = tid >> 5, lane = tid & 31;

    if (tid < 4) ((int4*)s_nbrs)[tid] = ((const int4*)(nbr + n * K))[tid];
    __syncthreads();

    // neighbors-of-neighbors, 2 per thread, straight into registers.
    // thread covers row a = tid>>3, entries c = 2*(tid&7), 2*(tid&7)+1
    const int a_row = s_nbrs[tid >> 3];
    const int2 nn = __ldg((const int2*)nbr + a_row * (K / 2) + (tid & 7));

    // feature gather: warp w covers rows {w, w+4, w+8, w+12};
    // each warp-load = one full 512B row (float4 per lane, coalesced)
    float4 acc = make_float4(0.f, 0.f, 0.f, 0.f);
    float s2 = 0.f;
    #pragma unroll
    for (int j = 0; j < 4; j++) {
        const int row = s_nbrs[w + 4 * j];
        float4 v = __ldg((const float4*)(x + row * F) + lane);
        acc.x += v.x; acc.y += v.y; acc.z += v.z; acc.w += v.w;
        s2 = fmaf(v.x, v.x, s2); s2 = fmaf(v.y, v.y, s2);
        s2 = fmaf(v.z, v.z, s2); s2 = fmaf(v.w, v.w, s2);
    }
    ((float4*)s_fpart[w])[lane] = acc;

    // all 16 neighbor ids into registers (4 broadcast LDS.128 per thread)
    int nb[K];
    {
        const int4 q0 = ((const int4*)s_nbrs)[0];
        const int4 q1 = ((const int4*)s_nbrs)[1];
        const int4 q2 = ((const int4*)s_nbrs)[2];
        const int4 q3 = ((const int4*)s_nbrs)[3];
        nb[0]=q0.x; nb[1]=q0.y; nb[2]=q0.z; nb[3]=q0.w;
        nb[4]=q1.x; nb[5]=q1.y; nb[6]=q1.z; nb[7]=q1.w;
        nb[8]=q2.x; nb[9]=q2.y; nb[10]=q2.z; nb[11]=q2.w;
        nb[12]=q3.x; nb[13]=q3.y; nb[14]=q3.z; nb[15]=q3.w;
    }

    // induced adjacency: C[a,b] = any_c (non[a][c] == nbrs[b]).
    // mask bit b set if either of this thread's two c-entries matches nbrs[b];
    // OR across the 8 lanes sharing row a, then popcount once per row.
    unsigned mask = 0u;
    #pragma unroll
    for (int b = 0; b < K; b++) {
        const unsigned hit = (nn.x == nb[b]) | (nn.y == nb[b]);
        mask |= hit << b;
    }
    mask |= __shfl_xor_sync(0xffffffffu, mask, 1);
    mask |= __shfl_xor_sync(0xffffffffu, mask, 2);
    mask |= __shfl_xor_sync(0xffffffffu, mask, 4);
    const int cnt = ((tid & 7) == 0) ? __popc(mask & 0xffffu) : 0;

    // joint warp reduction of s2 (for sq) and cnt (for mC)
    float cf = (float)cnt;
    #pragma unroll
    for (int off = 16; off; off >>= 1) {
        s2 += __shfl_down_sync(0xffffffffu, s2, off);
        cf += __shfl_down_sync(0xffffffffu, cf, off);
    }
    if (lane == 0) { s_rs2[w] = s2; s_rcnt[w] = cf; }
    __syncthreads();

    // per-dim feature mean across the 4 warps' partials
    const float fm = (s_fpart[0][tid] + s_fpart[1][tid] +
                      s_fpart[2][tid] + s_fpart[3][tid]) * (1.0f / K);
    s_fmean[tid] = fm;

    const float sq = (s_rs2[0] + s_rs2[1] + s_rs2[2] + s_rs2[3]) * (1.0f / K);
    const float mC = (s_rcnt[0] + s_rcnt[1] + s_rcnt[2] + s_rcnt[3]) * (1.0f / (K * K));
    __syncthreads();

    // fmean . tmean[t]: template t = tid>>3, dim chunk seg = tid&7 (16 dims each)
    const int t = tid >> 3, seg = tid & 7;
    const float4* fm4 = (const float4*)(s_fmean) + seg * 4;
    const float4* tm4 = (const float4*)(g_tmean + t * F) + seg * 4;
    float d = 0.f;
    #pragma unroll
    for (int j = 0; j < 4; j++) {
        const float4 a4 = fm4[j];
        const float4 b4 = __ldg(tm4 + j);
        d = fmaf(a4.x, b4.x, d); d = fmaf(a4.y, b4.y, d);
        d = fmaf(a4.z, b4.z, d); d = fmaf(a4.w, b4.w, d);
    }
    #pragma unroll
    for (int off = 4; off; off >>= 1)
        d += __shfl_down_sync(0xffffffffu, d, off, 8);

    if (seg == 0) {
        const float feat = sq + g_tsq[t] - 2.0f * d;
        const float st   = mC + g_mCt2[t] - 2.0f * mC * g_mCt[t];
        out[n * T + t] = 0.5f * feat + 0.5f * st;   // ALPHA = 0.5
    }
}

extern "C" void kernel_launch(void* const* d_in, const int* in_sizes, int n_in,
                              void* d_out, int out_size) {
    const float* x    = (const float*)d_in[0];
    const int*   edge = (const int*)  d_in[1];   // [2, N*K] int32
    const float* tmpl = (const float*)d_in[2];   // [T, M, M]
    const float* tf   = (const float*)d_in[3];   // [T, M, F]
    float* out = (float*)d_out;

    const int* nbr = edge + N_NODES * K;         // dst row

    tmpl_stats_kernel<<<1, 512>>>(tmpl, tf);
    ltfwg_kernel<<<N_NODES, 128>>>(x, nbr, out);
}

// round 6
// speedup vs baseline: 1.6873x; 1.6374x over previous
#include <cuda_runtime.h>

#define N_NODES 50000
#define K 16
#define F 128
#define T 16
#define M 8
#define NPB 4   // nodes per block, one warp each

// Precomputed template statistics (device scratch — no allocation allowed)
__device__ __align__(16) float g_tmean[T * F];
__device__ float g_tsq[T];
__device__ float g_mCt[T];
__device__ float g_mCt2[T];

__global__ __launch_bounds__(512) void tmpl_stats_kernel(
    const float* __restrict__ tmpl, const float* __restrict__ tf)
{
    const int tid = threadIdx.x;
    const int w = tid >> 5, lane = tid & 31;

    for (int i = tid; i < T * F; i += 512) {
        int t = i >> 7, f = i & (F - 1);
        float s = 0.f;
        #pragma unroll
        for (int m = 0; m < M; m++) s += tf[(t * M + m) * F + f];
        g_tmean[i] = s * (1.0f / M);
    }

    const int t = w;
    float s2 = 0.f;
    for (int e = lane; e < M * F; e += 32) {
        float v = tf[t * M * F + e];
        s2 = fmaf(v, v, s2);
    }
    float v0 = tmpl[t * 64 + lane];
    float v1 = tmpl[t * 64 + lane + 32];
    float sa = v0 + v1;
    float sb = v0 * v0 + v1 * v1;
    #pragma unroll
    for (int off = 16; off; off >>= 1) {
        s2 += __shfl_down_sync(0xffffffffu, s2, off);
        sa += __shfl_down_sync(0xffffffffu, sa, off);
        sb += __shfl_down_sync(0xffffffffu, sb, off);
    }
    if (lane == 0) {
        g_tsq[t]  = s2 * (1.0f / M);
        g_mCt[t]  = sa * (1.0f / 64.0f);
        g_mCt2[t] = sb * (1.0f / 64.0f);
    }
}

// 4 nodes per block; warp w owns node blockIdx.x*4 + w end-to-end,
// then a block-wide dot phase amortizes the tmean read over 4 nodes.
__global__ __launch_bounds__(128) void ltfwg_kernel(
    const float* __restrict__ x, const int* __restrict__ nbr,
    float* __restrict__ out)
{
    __shared__ __align__(16) int   s_nbrs[NPB][K];
    __shared__ __align__(16) float s_fmean[NPB][F];
    __shared__ float s_sq[NPB];
    __shared__ float s_mC[NPB];

    const int tid = threadIdx.x;
    const int w = tid >> 5, lane = tid & 31;
    const int n = blockIdx.x * NPB + w;

    if (lane < 4)
        ((int4*)s_nbrs[w])[lane] = ((const int4*)(nbr + n * K))[lane];
    __syncwarp();

    // all 16 neighbor ids into registers (broadcast LDS.128)
    int nb[K];
    {
        const int4 q0 = ((const int4*)s_nbrs[w])[0];
        const int4 q1 = ((const int4*)s_nbrs[w])[1];
        const int4 q2 = ((const int4*)s_nbrs[w])[2];
        const int4 q3 = ((const int4*)s_nbrs[w])[3];
        nb[0]=q0.x; nb[1]=q0.y; nb[2]=q0.z; nb[3]=q0.w;
        nb[4]=q1.x; nb[5]=q1.y; nb[6]=q1.z; nb[7]=q1.w;
        nb[8]=q2.x; nb[9]=q2.y; nb[10]=q2.z; nb[11]=q2.w;
        nb[12]=q3.x; nb[13]=q3.y; nb[14]=q3.z; nb[15]=q3.w;
    }

    // neighbors-of-neighbors: 4 lanes per row, int4 per lane; two loads
    // cover rows 0..7 and 8..15. Row ids via broadcast smem (no dyn reg idx).
    const int c4 = lane & 3;
    const int rA = s_nbrs[w][lane >> 2];
    const int rB = s_nbrs[w][8 + (lane >> 2)];
    const int4 nnA = __ldg((const int4*)nbr + rA * (K / 4) + c4);
    const int4 nnB = __ldg((const int4*)nbr + rB * (K / 4) + c4);

    // feature gather: 16 coalesced 512B row loads, accumulated in registers
    float4 fm = make_float4(0.f, 0.f, 0.f, 0.f);
    float s2 = 0.f;
    #pragma unroll
    for (int j = 0; j < K; j++) {
        const float4 v = __ldg((const float4*)(x + nb[j] * F) + lane);
        fm.x += v.x; fm.y += v.y; fm.z += v.z; fm.w += v.w;
        s2 = fmaf(v.x, v.x, s2); s2 = fmaf(v.y, v.y, s2);
        s2 = fmaf(v.z, v.z, s2); s2 = fmaf(v.w, v.w, s2);
    }

    // induced adjacency: per-lane 16-bit b-mask over its 4 c-entries,
    // OR across the 4 lanes sharing a row, popcount on row leader.
    unsigned m0 = 0u, m1 = 0u;
    #pragma unroll
    for (int b = 0; b < K; b++) {
        const unsigned h0 = (nnA.x == nb[b]) | (nnA.y == nb[b]) |
                            (nnA.z == nb[b]) | (nnA.w == nb[b]);
        const unsigned h1 = (nnB.x == nb[b]) | (nnB.y == nb[b]) |
                            (nnB.z == nb[b]) | (nnB.w == nb[b]);
        m0 |= h0 << b;
        m1 |= h1 << b;
    }
    m0 |= __shfl_xor_sync(0xffffffffu, m0, 1);
    m0 |= __shfl_xor_sync(0xffffffffu, m0, 2);
    m1 |= __shfl_xor_sync(0xffffffffu, m1, 1);
    m1 |= __shfl_xor_sync(0xffffffffu, m1, 2);
    float cf = (c4 == 0) ? (float)(__popc(m0 & 0xffffu) + __popc(m1 & 0xffffu)) : 0.f;

    // joint warp reduction (sq and edge count)
    #pragma unroll
    for (int off = 16; off; off >>= 1) {
        s2 += __shfl_down_sync(0xffffffffu, s2, off);
        cf += __shfl_down_sync(0xffffffffu, cf, off);
    }
    if (lane == 0) {
        s_sq[w] = s2 * (1.0f / K);
        s_mC[w] = cf * (1.0f / (K * K));
    }
    ((float4*)s_fmean[w])[lane] = make_float4(fm.x * (1.0f / K), fm.y * (1.0f / K),
                                              fm.z * (1.0f / K), fm.w * (1.0f / K));
    __syncthreads();

    // dot phase: thread -> (t = tid>>3, seg = tid&7); tmean loaded ONCE,
    // reused for the block's 4 nodes.
    const int t = tid >> 3, seg = tid & 7;
    float4 tm[4];
    {
        const float4* tm4 = (const float4*)(g_tmean + t * F) + seg * 4;
        #pragma unroll
        for (int j = 0; j < 4; j++) tm[j] = __ldg(tm4 + j);
    }
    const float tsq  = g_tsq[t];
    const float mCt  = g_mCt[t];
    const float mCt2 = g_mCt2[t];

    #pragma unroll
    for (int node = 0; node < NPB; node++) {
        const float4* fm4 = (const float4*)(s_fmean[node]) + seg * 4;
        float d = 0.f;
        #pragma unroll
        for (int j = 0; j < 4; j++) {
            const float4 a4 = fm4[j];
            d = fmaf(a4.x, tm[j].x, d); d = fmaf(a4.y, tm[j].y, d);
            d = fmaf(a4.z, tm[j].z, d); d = fmaf(a4.w, tm[j].w, d);
        }
        #pragma unroll
        for (int off = 4; off; off >>= 1)
            d += __shfl_down_sync(0xffffffffu, d, off, 8);

        if (seg == 0) {
            const float sq = s_sq[node];
            const float mC = s_mC[node];
            const float feat = sq + tsq - 2.0f * d;
            const float st   = mC + mCt2 - 2.0f * mC * mCt;
            out[(blockIdx.x * NPB + node) * T + t] = 0.5f * feat + 0.5f * st;
        }
    }
}

extern "C" void kernel_launch(void* const* d_in, const int* in_sizes, int n_in,
                              void* d_out, int out_size) {
    const float* x    = (const float*)d_in[0];
    const int*   edge = (const int*)  d_in[1];   // [2, N*K] int32
    const float* tmpl = (const float*)d_in[2];   // [T, M, M]
    const float* tf   = (const float*)d_in[3];   // [T, M, F]
    float* out = (float*)d_out;

    const int* nbr = edge + N_NODES * K;         // dst row

    tmpl_stats_kernel<<<1, 512>>>(tmpl, tf);
    ltfwg_kernel<<<N_NODES / NPB, 128>>>(x, nbr, out);
}

// round 8
// speedup vs baseline: 2.7816x; 1.6485x over previous
#include <cuda_runtime.h>

#define N_NODES 50000
#define K 16
#define F 128
#define T 16
#define M 8
#define NPB 4          // nodes per block (one warp each) in main kernel
#define PRE_BLOCKS 512
#define PRE_THREADS 256
#define PRE_WARPS (PRE_BLOCKS * PRE_THREADS / 32)

// Device scratch (no allocation allowed)
__device__ __align__(16) float g_tmean[T * F];
__device__ __align__(16) float g_tsq[T];
__device__ __align__(16) float g_mCt[T];
__device__ __align__(16) float g_mCt2[T];
// packed per-node row: [ y[0..15] , z , pad[15] ]  -> 128B, line-aligned
__device__ __align__(128) float g_yz[N_NODES * 32];

__global__ __launch_bounds__(512) void tmpl_stats_kernel(
    const float* __restrict__ tmpl, const float* __restrict__ tf)
{
    const int tid = threadIdx.x;
    const int w = tid >> 5, lane = tid & 31;

    for (int i = tid; i < T * F; i += 512) {
        int t = i >> 7, f = i & (F - 1);
        float s = 0.f;
        #pragma unroll
        for (int m = 0; m < M; m++) s += tf[(t * M + m) * F + f];
        g_tmean[i] = s * (1.0f / M);
    }

    const int t = w;
    float s2 = 0.f;
    for (int e = lane; e < M * F; e += 32) {
        float v = tf[t * M * F + e];
        s2 = fmaf(v, v, s2);
    }
    float v0 = tmpl[t * 64 + lane];
    float v1 = tmpl[t * 64 + lane + 32];
    float sa = v0 + v1;
    float sb = v0 * v0 + v1 * v1;
    #pragma unroll
    for (int off = 16; off; off >>= 1) {
        s2 += __shfl_down_sync(0xffffffffu, s2, off);
        sa += __shfl_down_sync(0xffffffffu, sa, off);
        sb += __shfl_down_sync(0xffffffffu, sb, off);
    }
    if (lane == 0) {
        g_tsq[t]  = s2 * (1.0f / M);
        g_mCt[t]  = sa * (1.0f / 64.0f);
        g_mCt2[t] = sb * (1.0f / 64.0f);
    }
}

// Precompute y[i][t] = x[i].tmean[t], z[i] = ||x_i||^2.
// Warp per row; W distributed: lane L holds tmean[t][4L..4L+3] for all 16 t.
__global__ __launch_bounds__(PRE_THREADS) void precompute_kernel(
    const float* __restrict__ x)
{
    const int lane = threadIdx.x & 31;
    const int gw = (blockIdx.x * PRE_THREADS + threadIdx.x) >> 5;

    // load W slice: 16 x float4 per lane (one-time per warp)
    float4 wv[T];
    #pragma unroll
    for (int t = 0; t < T; t++)
        wv[t] = __ldg((const float4*)(g_tmean + t * F) + lane);

    for (int row = gw; row < N_NODES; row += PRE_WARPS) {
        const float4 xv = __ldg((const float4*)(x + row * F) + lane);
        float a[T];
        #pragma unroll
        for (int t = 0; t < T; t++) {
            float d = xv.x * wv[t].x;
            d = fmaf(xv.y, wv[t].y, d);
            d = fmaf(xv.z, wv[t].z, d);
            d = fmaf(xv.w, wv[t].w, d);
            a[t] = d;
        }
        float s2 = xv.x * xv.x;
        s2 = fmaf(xv.y, xv.y, s2);
        s2 = fmaf(xv.z, xv.z, s2);
        s2 = fmaf(xv.w, xv.w, s2);

        // multi-value butterfly: offsets 16,8,4,2 halve the 16 accs,
        // then offset 1 folds the last lane pair.
        #pragma unroll
        for (int r = 0; r < 4; r++) {
            const int off = 16 >> r;
            const int half = 8 >> r;
            const bool up = (lane & off) != 0;
            #pragma unroll
            for (int i = 0; i < 8; i++) {
                if (i < half) {
                    float send = up ? a[i] : a[i + half];
                    float got = __shfl_xor_sync(0xffffffffu, send, off);
                    a[i] = (up ? a[i + half] : a[i]) + got;
                }
            }
        }
        a[0] += __shfl_xor_sync(0xffffffffu, a[0], 1);

        #pragma unroll
        for (int off = 16; off; off >>= 1)
            s2 += __shfl_xor_sync(0xffffffffu, s2, off);

        // lane L (even) holds t = bit pattern of lane bits 4..1
        const int t = (((lane >> 4) & 1) << 3) | (((lane >> 3) & 1) << 2) |
                      (((lane >> 2) & 1) << 1) | ((lane >> 1) & 1);
        if ((lane & 1) == 0) g_yz[row * 32 + t] = a[0];
        if (lane == 0)       g_yz[row * 32 + 16] = s2;
    }
}

// Main kernel: warp per node, 4 nodes per block. No x access at all.
__global__ __launch_bounds__(128) void ltfwg_kernel(
    const int* __restrict__ nbr, float* __restrict__ out)
{
    __shared__ __align__(16) int s_nbrs[NPB][K];

    const int tid = threadIdx.x;
    const int w = tid >> 5, lane = tid & 31;
    const int n = blockIdx.x * NPB + w;

    if (lane < 4)
        ((int4*)s_nbrs[w])[lane] = ((const int4*)(nbr + n * K))[lane];
    __syncwarp();

    // all 16 neighbor ids into registers (broadcast LDS.128)
    int nb[K];
    {
        const int4 q0 = ((const int4*)s_nbrs[w])[0];
        const int4 q1 = ((const int4*)s_nbrs[w])[1];
        const int4 q2 = ((const int4*)s_nbrs[w])[2];
        const int4 q3 = ((const int4*)s_nbrs[w])[3];
        nb[0]=q0.x; nb[1]=q0.y; nb[2]=q0.z; nb[3]=q0.w;
        nb[4]=q1.x; nb[5]=q1.y; nb[6]=q1.z; nb[7]=q1.w;
        nb[8]=q2.x; nb[9]=q2.y; nb[10]=q2.z; nb[11]=q2.w;
        nb[12]=q3.x; nb[13]=q3.y; nb[14]=q3.z; nb[15]=q3.w;
    }

    // neighbors-of-neighbors: 4 lanes per row x int4; rows 0-7 and 8-15
    const int c4 = lane & 3;
    const int rA = s_nbrs[w][lane >> 2];
    const int rB = s_nbrs[w][8 + (lane >> 2)];
    const int4 nnA = __ldg((const int4*)nbr + rA * (K / 4) + c4);
    const int4 nnB = __ldg((const int4*)nbr + rB * (K / 4) + c4);

    // yz gather: 8 lanes per row (sub = lane&7 -> float4 chunk), 4 rows per
    // warp-load, 4 iterations cover 16 neighbors. Each row = exactly 1 line.
    const int sub = lane & 7;
    float4 acc = make_float4(0.f, 0.f, 0.f, 0.f);
    #pragma unroll
    for (int p = 0; p < 4; p++) {
        const int row = s_nbrs[w][p * 4 + (lane >> 3)];
        const float4 v = __ldg((const float4*)(g_yz + row * 32) + sub);
        acc.x += v.x; acc.y += v.y; acc.z += v.z; acc.w += v.w;
    }
    // reduce across the 4 lanes sharing sub (stride 8)
    #pragma unroll
    for (int off = 8; off <= 16; off <<= 1) {
        acc.x += __shfl_xor_sync(0xffffffffu, acc.x, off);
        acc.y += __shfl_xor_sync(0xffffffffu, acc.y, off);
        acc.z += __shfl_xor_sync(0xffffffffu, acc.z, off);
        acc.w += __shfl_xor_sync(0xffffffffu, acc.w, off);
    }
    // lanes 0-3: y sums for t = lane*4..lane*4+3 ; lane 4: z sum in .x
    const float sq = __shfl_sync(0xffffffffu, acc.x, 4) * (1.0f / K);

    // induced adjacency: per-lane 16-bit b-mask, OR across 4 lanes per row
    unsigned m0 = 0u, m1 = 0u;
    #pragma unroll
    for (int b = 0; b < K; b++) {
        const unsigned h0 = (nnA.x == nb[b]) | (nnA.y == nb[b]) |
                            (nnA.z == nb[b]) | (nnA.w == nb[b]);
        const unsigned h1 = (nnB.x == nb[b]) | (nnB.y == nb[b]) |
                            (nnB.z == nb[b]) | (nnB.w == nb[b]);
        m0 |= h0 << b;
        m1 |= h1 << b;
    }
    m0 |= __shfl_xor_sync(0xffffffffu, m0, 1);
    m0 |= __shfl_xor_sync(0xffffffffu, m0, 2);
    m1 |= __shfl_xor_sync(0xffffffffu, m1, 1);
    m1 |= __shfl_xor_sync(0xffffffffu, m1, 2);
    int cnt = (c4 == 0) ? (__popc(m0 & 0xffffu) + __popc(m1 & 0xffffu)) : 0;
    #pragma unroll
    for (int off = 4; off <= 16; off <<= 1)
        cnt += __shfl_xor_sync(0xffffffffu, cnt, off);
    const float mC = (float)cnt * (1.0f / (K * K));

    // finalize: lanes 0-3 each produce 4 outputs (float4 store, 64B total)
    if (lane < 4) {
        const float4 tsq4  = __ldg((const float4*)g_tsq  + lane);
        const float4 mCt4  = __ldg((const float4*)g_mCt  + lane);
        const float4 mCt24 = __ldg((const float4*)g_mCt2 + lane);
        const float stc = mC;  // struct term common factor
        float4 o;
        o.x = 0.5f * (sq + tsq4.x - 2.0f * acc.x * (1.0f / K)) +
              0.5f * (stc + mCt24.x - 2.0f * stc * mCt4.x);
        o.y = 0.5f * (sq + tsq4.y - 2.0f * acc.y * (1.0f / K)) +
              0.5f * (stc + mCt24.y - 2.0f * stc * mCt4.y);
        o.z = 0.5f * (sq + tsq4.z - 2.0f * acc.z * (1.0f / K)) +
              0.5f * (stc + mCt24.z - 2.0f * stc * mCt4.z);
        o.w = 0.5f * (sq + tsq4.w - 2.0f * acc.w * (1.0f / K)) +
              0.5f * (stc + mCt24.w - 2.0f * stc * mCt4.w);
        ((float4*)(out + n * T))[lane] = o;
    }
}

extern "C" void kernel_launch(void* const* d_in, const int* in_sizes, int n_in,
                              void* d_out, int out_size) {
    const float* x    = (const float*)d_in[0];
    const int*   edge = (const int*)  d_in[1];   // [2, N*K] int32
    const float* tmpl = (const float*)d_in[2];   // [T, M, M]
    const float* tf   = (const float*)d_in[3];   // [T, M, F]
    float* out = (float*)d_out;

    const int* nbr = edge + N_NODES * K;         // dst row

    tmpl_stats_kernel<<<1, 512>>>(tmpl, tf);
    precompute_kernel<<<PRE_BLOCKS, PRE_THREADS>>>(x);
    ltfwg_kernel<<<N_NODES / NPB, 128>>>(nbr, out);
}

// round 11
// speedup vs baseline: 2.7867x; 1.0019x over previous
#include <cuda_runtime.h>

#define N_NODES 50000
#define K 16
#define F 128
#define T 16
#define M 8
#define NPB 8          // nodes per block (one warp each) in main kernel
#define PRE_BLOCKS 512
#define PRE_THREADS 256
#define PRE_WARPS (PRE_BLOCKS * PRE_THREADS / 32)

// Device scratch (no allocation allowed)
__device__ __align__(16) float g_tsq[T];
__device__ __align__(16) float g_mCt[T];
__device__ __align__(16) float g_mCt2[T];
// packed per-node row: [ y[0..15] , z , pad[15] ]  -> 128B, line-aligned
__device__ __align__(128) float g_yz[N_NODES * 32];

// Fused: per-block tmean (smem) + y/z precompute; block 0 also emits the
// per-template scalars used by the main kernel's finalize.
__global__ __launch_bounds__(PRE_THREADS) void precompute_kernel(
    const float* __restrict__ x, const float* __restrict__ tmpl,
    const float* __restrict__ tf)
{
    __shared__ __align__(16) float s_tmean[T * F];   // 8 KB

    const int tid = threadIdx.x;
    const int w = tid >> 5, lane = tid & 31;

    // block-local tmean[t][f] = mean over m of tf[t][m][f]  (tf is L2-hot)
    for (int i = tid; i < T * F; i += PRE_THREADS) {
        const int t = i >> 7, f = i & (F - 1);
        float s = 0.f;
        #pragma unroll
        for (int m = 0; m < M; m++) s += __ldg(tf + (t * M + m) * F + f);
        s_tmean[i] = s * (1.0f / M);
    }

    // block 0: per-template scalars (warp w covers t = w, w+8)
    if (blockIdx.x == 0) {
        #pragma unroll
        for (int t = w; t < T; t += PRE_THREADS / 32) {
            float s2 = 0.f;
            for (int e = lane; e < M * F; e += 32) {
                const float v = __ldg(tf + t * M * F + e);
                s2 = fmaf(v, v, s2);
            }
            const float v0 = __ldg(tmpl + t * 64 + lane);
            const float v1 = __ldg(tmpl + t * 64 + lane + 32);
            float sa = v0 + v1;
            float sb = v0 * v0 + v1 * v1;
            #pragma unroll
            for (int off = 16; off; off >>= 1) {
                s2 += __shfl_down_sync(0xffffffffu, s2, off);
                sa += __shfl_down_sync(0xffffffffu, sa, off);
                sb += __shfl_down_sync(0xffffffffu, sb, off);
            }
            if (lane == 0) {
                g_tsq[t]  = s2 * (1.0f / M);
                g_mCt[t]  = sa * (1.0f / 64.0f);
                g_mCt2[t] = sb * (1.0f / 64.0f);
            }
        }
    }
    __syncthreads();

    // W slice into registers: lane L holds tmean[t][4L..4L+3] for all 16 t
    float4 wv[T];
    #pragma unroll
    for (int t = 0; t < T; t++)
        wv[t] = ((const float4*)(s_tmean + t * F))[lane];

    const int gw = (blockIdx.x * PRE_THREADS + tid) >> 5;
    for (int row = gw; row < N_NODES; row += PRE_WARPS) {
        const float4 xv = __ldg((const float4*)(x + row * F) + lane);
        float a[T];
        #pragma unroll
        for (int t = 0; t < T; t++) {
            float d = xv.x * wv[t].x;
            d = fmaf(xv.y, wv[t].y, d);
            d = fmaf(xv.z, wv[t].z, d);
            d = fmaf(xv.w, wv[t].w, d);
            a[t] = d;
        }
        float s2 = xv.x * xv.x;
        s2 = fmaf(xv.y, xv.y, s2);
        s2 = fmaf(xv.z, xv.z, s2);
        s2 = fmaf(xv.w, xv.w, s2);

        // multi-value butterfly: offsets 16,8,4,2 halve the 16 accs,
        // then offset 1 folds the last lane pair.
        #pragma unroll
        for (int r = 0; r < 4; r++) {
            const int off = 16 >> r;
            const int half = 8 >> r;
            const bool up = (lane & off) != 0;
            #pragma unroll
            for (int i = 0; i < 8; i++) {
                if (i < half) {
                    float send = up ? a[i] : a[i + half];
                    float got = __shfl_xor_sync(0xffffffffu, send, off);
                    a[i] = (up ? a[i + half] : a[i]) + got;
                }
            }
        }
        a[0] += __shfl_xor_sync(0xffffffffu, a[0], 1);

        #pragma unroll
        for (int off = 16; off; off >>= 1)
            s2 += __shfl_xor_sync(0xffffffffu, s2, off);

        // lane L (even) holds t = bit pattern of lane bits 4..1
        const int t = (((lane >> 4) & 1) << 3) | (((lane >> 3) & 1) << 2) |
                      (((lane >> 2) & 1) << 1) | ((lane >> 1) & 1);
        if ((lane & 1) == 0) g_yz[row * 32 + t] = a[0];
        if (lane == 0)       g_yz[row * 32 + 16] = s2;
    }
}

// Main kernel: warp per node, 8 nodes per block. No x access at all.
__global__ __launch_bounds__(32 * NPB) void ltfwg_kernel(
    const int* __restrict__ nbr, float* __restrict__ out)
{
    __shared__ __align__(16) int s_nbrs[NPB][K];

    const int tid = threadIdx.x;
    const int w = tid >> 5, lane = tid & 31;
    const int n = blockIdx.x * NPB + w;

    if (lane < 4)
        ((int4*)s_nbrs[w])[lane] = ((const int4*)(nbr + n * K))[lane];
    __syncwarp();

    // all 16 neighbor ids into registers (broadcast LDS.128)
    int nb[K];
    {
        const int4 q0 = ((const int4*)s_nbrs[w])[0];
        const int4 q1 = ((const int4*)s_nbrs[w])[1];
        const int4 q2 = ((const int4*)s_nbrs[w])[2];
        const int4 q3 = ((const int4*)s_nbrs[w])[3];
        nb[0]=q0.x; nb[1]=q0.y; nb[2]=q0.z; nb[3]=q0.w;
        nb[4]=q1.x; nb[5]=q1.y; nb[6]=q1.z; nb[7]=q1.w;
        nb[8]=q2.x; nb[9]=q2.y; nb[10]=q2.z; nb[11]=q2.w;
        nb[12]=q3.x; nb[13]=q3.y; nb[14]=q3.z; nb[15]=q3.w;
    }

    // neighbors-of-neighbors: 4 lanes per row x int4; rows 0-7 and 8-15
    const int c4 = lane & 3;
    const int rA = s_nbrs[w][lane >> 2];
    const int rB = s_nbrs[w][8 + (lane >> 2)];
    const int4 nnA = __ldg((const int4*)nbr + rA * (K / 4) + c4);
    const int4 nnB = __ldg((const int4*)nbr + rB * (K / 4) + c4);

    // yz gather: 8 lanes per row (sub = lane&7 -> float4 chunk), 4 rows per
    // warp-load, 4 iterations cover 16 neighbors. Each row = exactly 1 line.
    const int sub = lane & 7;
    float4 acc = make_float4(0.f, 0.f, 0.f, 0.f);
    #pragma unroll
    for (int p = 0; p < 4; p++) {
        const int row = s_nbrs[w][p * 4 + (lane >> 3)];
        const float4 v = __ldg((const float4*)(g_yz + row * 32) + sub);
        acc.x += v.x; acc.y += v.y; acc.z += v.z; acc.w += v.w;
    }
    // reduce across the 4 lanes sharing sub (stride 8)
    #pragma unroll
    for (int off = 8; off <= 16; off <<= 1) {
        acc.x += __shfl_xor_sync(0xffffffffu, acc.x, off);
        acc.y += __shfl_xor_sync(0xffffffffu, acc.y, off);
        acc.z += __shfl_xor_sync(0xffffffffu, acc.z, off);
        acc.w += __shfl_xor_sync(0xffffffffu, acc.w, off);
    }
    // lanes 0-3: y sums for t = lane*4..lane*4+3 ; lane 4: z sum in .x
    const float sq = __shfl_sync(0xffffffffu, acc.x, 4) * (1.0f / K);

    // induced adjacency: per-lane 16-bit b-mask, OR across 4 lanes per row
    unsigned m0 = 0u, m1 = 0u;
    #pragma unroll
    for (int b = 0; b < K; b++) {
        const unsigned h0 = (nnA.x == nb[b]) | (nnA.y == nb[b]) |
                            (nnA.z == nb[b]) | (nnA.w == nb[b]);
        const unsigned h1 = (nnB.x == nb[b]) | (nnB.y == nb[b]) |
                            (nnB.z == nb[b]) | (nnB.w == nb[b]);
        m0 |= h0 << b;
        m1 |= h1 << b;
    }
    m0 |= __shfl_xor_sync(0xffffffffu, m0, 1);
    m0 |= __shfl_xor_sync(0xffffffffu, m0, 2);
    m1 |= __shfl_xor_sync(0xffffffffu, m1, 1);
    m1 |= __shfl_xor_sync(0xffffffffu, m1, 2);
    int cnt = (c4 == 0) ? (__popc(m0 & 0xffffu) + __popc(m1 & 0xffffu)) : 0;
    #pragma unroll
    for (int off = 4; off <= 16; off <<= 1)
        cnt += __shfl_xor_sync(0xffffffffu, cnt, off);
    const float mC = (float)cnt * (1.0f / (K * K));

    // finalize: lanes 0-3 each produce 4 outputs (float4 store, 64B total)
    if (lane < 4) {
        const float4 tsq4  = __ldg((const float4*)g_tsq  + lane);
        const float4 mCt4  = __ldg((const float4*)g_mCt  + lane);
        const float4 mCt24 = __ldg((const float4*)g_mCt2 + lane);
        const float stc = mC;  // struct term common factor
        float4 o;
        o.x = 0.5f * (sq + tsq4.x - 2.0f * acc.x * (1.0f / K)) +
              0.5f * (stc + mCt24.x - 2.0f * stc * mCt4.x);
        o.y = 0.5f * (sq + tsq4.y - 2.0f * acc.y * (1.0f / K)) +
              0.5f * (stc + mCt24.y - 2.0f * stc * mCt4.y);
        o.z = 0.5f * (sq + tsq4.z - 2.0f * acc.z * (1.0f / K)) +
              0.5f * (stc + mCt24.z - 2.0f * stc * mCt4.z);
        o.w = 0.5f * (sq + tsq4.w - 2.0f * acc.w * (1.0f / K)) +
              0.5f * (stc + mCt24.w - 2.0f * stc * mCt4.w);
        ((float4*)(out + n * T))[lane] = o;
    }
}

extern "C" void kernel_launch(void* const* d_in, const int* in_sizes, int n_in,
                              void* d_out, int out_size) {
    const float* x    = (const float*)d_in[0];
    const int*   edge = (const int*)  d_in[1];   // [2, N*K] int32
    const float* tmpl = (const float*)d_in[2];   // [T, M, M]
    const float* tf   = (const float*)d_in[3];   // [T, M, F]
    float* out = (float*)d_out;

    const int* nbr = edge + N_NODES * K;         // dst row

    precompute_kernel<<<PRE_BLOCKS, PRE_THREADS>>>(x, tmpl, tf);
    ltfwg_kernel<<<N_NODES / NPB, 32 * NPB>>>(nbr, out);
}

// round 15
// speedup vs baseline: 3.5200x; 1.2631x over previous
#include <cuda_runtime.h>

#define N_NODES 50000
#define K 16
#define F 128
#define T 16
#define M 8
#define NPB 8          // nodes per block (one warp each) in main kernel
#define PRE_BLOCKS 512
#define PRE_THREADS 256
#define PRE_WARPS (PRE_BLOCKS * PRE_THREADS / 32)

// Device scratch (no allocation allowed)
__device__ __align__(16) float g_tsq[T];
__device__ __align__(16) float g_mCt[T];
__device__ __align__(16) float g_mCt2[T];
// packed per-node row: [ y[0..15] , z , pad[15] ]  -> 128B, line-aligned
__device__ __align__(128) float g_yz[N_NODES * 32];

// 4-way compare-OR chain + predicated mask-bit set: exactly 5 SASS instr.
// BIT is a template parameter so the "n" immediate constraint is a genuine
// integral constant expression.
template <int BIT>
__device__ __forceinline__ void adj_cmp4(unsigned& mask, const int4& q, int v)
{
    asm("{\n\t.reg .pred p;\n\t"
        "setp.eq.s32 p, %1, %5;\n\t"
        "setp.eq.or.s32 p, %2, %5, p;\n\t"
        "setp.eq.or.s32 p, %3, %5, p;\n\t"
        "setp.eq.or.s32 p, %4, %5, p;\n\t"
        "@p or.b32 %0, %0, %6;\n\t}"
        : "+r"(mask)
        : "r"(q.x), "r"(q.y), "r"(q.z), "r"(q.w),
          "r"(v), "n"(1u << BIT));
}

template <int B>
__device__ __forceinline__ void adj_loop(unsigned& m0, unsigned& m1,
                                         const int4& nnA, const int4& nnB,
                                         const int* nb)
{
    adj_cmp4<B>(m0, nnA, nb[B]);
    adj_cmp4<B>(m1, nnB, nb[B]);
    if constexpr (B + 1 < K) adj_loop<B + 1>(m0, m1, nnA, nnB, nb);
}

// Fused: per-block tmean (smem) + y/z precompute; block 0 also emits the
// per-template scalars used by the main kernel's finalize.
__global__ __launch_bounds__(PRE_THREADS) void precompute_kernel(
    const float* __restrict__ x, const float* __restrict__ tmpl,
    const float* __restrict__ tf)
{
    __shared__ __align__(16) float s_tmean[T * F];   // 8 KB

    const int tid = threadIdx.x;
    const int w = tid >> 5, lane = tid & 31;

    // block-local tmean[t][f] = mean over m of tf[t][m][f]  (tf is L2-hot)
    for (int i = tid; i < T * F; i += PRE_THREADS) {
        const int t = i >> 7, f = i & (F - 1);
        float s = 0.f;
        #pragma unroll
        for (int m = 0; m < M; m++) s += __ldg(tf + (t * M + m) * F + f);
        s_tmean[i] = s * (1.0f / M);
    }

    // block 0: per-template scalars (warp w covers t = w, w+8)
    if (blockIdx.x == 0) {
        #pragma unroll
        for (int t = w; t < T; t += PRE_THREADS / 32) {
            float s2 = 0.f;
            for (int e = lane; e < M * F; e += 32) {
                const float v = __ldg(tf + t * M * F + e);
                s2 = fmaf(v, v, s2);
            }
            const float v0 = __ldg(tmpl + t * 64 + lane);
            const float v1 = __ldg(tmpl + t * 64 + lane + 32);
            float sa = v0 + v1;
            float sb = v0 * v0 + v1 * v1;
            #pragma unroll
            for (int off = 16; off; off >>= 1) {
                s2 += __shfl_down_sync(0xffffffffu, s2, off);
                sa += __shfl_down_sync(0xffffffffu, sa, off);
                sb += __shfl_down_sync(0xffffffffu, sb, off);
            }
            if (lane == 0) {
                g_tsq[t]  = s2 * (1.0f / M);
                g_mCt[t]  = sa * (1.0f / 64.0f);
                g_mCt2[t] = sb * (1.0f / 64.0f);
            }
        }
    }
    __syncthreads();

    // W slice into registers: lane L holds tmean[t][4L..4L+3] for all 16 t
    float4 wv[T];
    #pragma unroll
    for (int t = 0; t < T; t++)
        wv[t] = ((const float4*)(s_tmean + t * F))[lane];

    const int gw = (blockIdx.x * PRE_THREADS + tid) >> 5;
    for (int row = gw; row < N_NODES; row += PRE_WARPS) {
        const float4 xv = __ldg((const float4*)(x + row * F) + lane);
        float a[T];
        #pragma unroll
        for (int t = 0; t < T; t++) {
            float d = xv.x * wv[t].x;
            d = fmaf(xv.y, wv[t].y, d);
            d = fmaf(xv.z, wv[t].z, d);
            d = fmaf(xv.w, wv[t].w, d);
            a[t] = d;
        }
        float s2 = xv.x * xv.x;
        s2 = fmaf(xv.y, xv.y, s2);
        s2 = fmaf(xv.z, xv.z, s2);
        s2 = fmaf(xv.w, xv.w, s2);

        // multi-value butterfly: offsets 16,8,4,2 halve the 16 accs,
        // then offset 1 folds the last lane pair.
        #pragma unroll
        for (int r = 0; r < 4; r++) {
            const int off = 16 >> r;
            const int half = 8 >> r;
            const bool up = (lane & off) != 0;
            #pragma unroll
            for (int i = 0; i < 8; i++) {
                if (i < half) {
                    float send = up ? a[i] : a[i + half];
                    float got = __shfl_xor_sync(0xffffffffu, send, off);
                    a[i] = (up ? a[i + half] : a[i]) + got;
                }
            }
        }
        a[0] += __shfl_xor_sync(0xffffffffu, a[0], 1);

        #pragma unroll
        for (int off = 16; off; off >>= 1)
            s2 += __shfl_xor_sync(0xffffffffu, s2, off);

        // lane L (even) holds t = bit pattern of lane bits 4..1
        const int t = (((lane >> 4) & 1) << 3) | (((lane >> 3) & 1) << 2) |
                      (((lane >> 2) & 1) << 1) | ((lane >> 1) & 1);
        if ((lane & 1) == 0) g_yz[row * 32 + t] = a[0];
        if (lane == 0)       g_yz[row * 32 + 16] = s2;
    }
}

// Main kernel: warp per node, 8 nodes per block. No x access at all.
__global__ __launch_bounds__(32 * NPB) void ltfwg_kernel(
    const int* __restrict__ nbr, float* __restrict__ out)
{
    __shared__ __align__(16) int s_nbrs[NPB][K];

    const int tid = threadIdx.x;
    const int w = tid >> 5, lane = tid & 31;
    const int n = blockIdx.x * NPB + w;

    if (lane < 4)
        ((int4*)s_nbrs[w])[lane] = ((const int4*)(nbr + n * K))[lane];
    __syncwarp();

    // all 16 neighbor ids into registers (broadcast LDS.128)
    int nb[K];
    {
        const int4 q0 = ((const int4*)s_nbrs[w])[0];
        const int4 q1 = ((const int4*)s_nbrs[w])[1];
        const int4 q2 = ((const int4*)s_nbrs[w])[2];
        const int4 q3 = ((const int4*)s_nbrs[w])[3];
        nb[0]=q0.x; nb[1]=q0.y; nb[2]=q0.z; nb[3]=q0.w;
        nb[4]=q1.x; nb[5]=q1.y; nb[6]=q1.z; nb[7]=q1.w;
        nb[8]=q2.x; nb[9]=q2.y; nb[10]=q2.z; nb[11]=q2.w;
        nb[12]=q3.x; nb[13]=q3.y; nb[14]=q3.z; nb[15]=q3.w;
    }

    // neighbors-of-neighbors: 4 lanes per row x int4; rows 0-7 and 8-15
    const int c4 = lane & 3;
    const int rA = s_nbrs[w][lane >> 2];
    const int rB = s_nbrs[w][8 + (lane >> 2)];
    const int4 nnA = __ldg((const int4*)nbr + rA * (K / 4) + c4);
    const int4 nnB = __ldg((const int4*)nbr + rB * (K / 4) + c4);

    // yz gather: 8 lanes per row (sub = lane&7 -> float4 chunk), 4 rows per
    // warp-load, 4 iterations cover 16 neighbors. Each row = exactly 1 line.
    const int sub = lane & 7;
    float4 acc = make_float4(0.f, 0.f, 0.f, 0.f);
    #pragma unroll
    for (int p = 0; p < 4; p++) {
        const int row = s_nbrs[w][p * 4 + (lane >> 3)];
        const float4 v = __ldg((const float4*)(g_yz + row * 32) + sub);
        acc.x += v.x; acc.y += v.y; acc.z += v.z; acc.w += v.w;
    }
    // reduce across the 4 lanes sharing sub (stride 8)
    #pragma unroll
    for (int off = 8; off <= 16; off <<= 1) {
        acc.x += __shfl_xor_sync(0xffffffffu, acc.x, off);
        acc.y += __shfl_xor_sync(0xffffffffu, acc.y, off);
        acc.z += __shfl_xor_sync(0xffffffffu, acc.z, off);
        acc.w += __shfl_xor_sync(0xffffffffu, acc.w, off);
    }
    // lanes 0-3: y sums for t = lane*4..lane*4+3 ; lane 4: z sum in .x
    const float sq = __shfl_sync(0xffffffffu, acc.x, 4) * (1.0f / K);

    // induced adjacency: per-lane 16-bit b-mask via chained setp.eq.or
    // (5 SASS instr per mask update), OR across 4 lanes per row.
    unsigned m0 = 0u, m1 = 0u;
    adj_loop<0>(m0, m1, nnA, nnB, nb);
    m0 |= __shfl_xor_sync(0xffffffffu, m0, 1);
    m0 |= __shfl_xor_sync(0xffffffffu, m0, 2);
    m1 |= __shfl_xor_sync(0xffffffffu, m1, 1);
    m1 |= __shfl_xor_sync(0xffffffffu, m1, 2);
    int cnt = (c4 == 0) ? (__popc(m0 & 0xffffu) + __popc(m1 & 0xffffu)) : 0;
    cnt = __reduce_add_sync(0xffffffffu, cnt);
    const float mC = (float)cnt * (1.0f / (K * K));

    // finalize: lanes 0-3 each produce 4 outputs (float4 store, 64B total)
    if (lane < 4) {
        const float4 tsq4  = __ldg((const float4*)g_tsq  + lane);
        const float4 mCt4  = __ldg((const float4*)g_mCt  + lane);
        const float4 mCt24 = __ldg((const float4*)g_mCt2 + lane);
        const float stc = mC;  // struct term common factor
        float4 o;
        o.x = 0.5f * (sq + tsq4.x - 2.0f * acc.x * (1.0f / K)) +
              0.5f * (stc + mCt24.x - 2.0f * stc * mCt4.x);
        o.y = 0.5f * (sq + tsq4.y - 2.0f * acc.y * (1.0f / K)) +
              0.5f * (stc + mCt24.y - 2.0f * stc * mCt4.y);
        o.z = 0.5f * (sq + tsq4.z - 2.0f * acc.z * (1.0f / K)) +
              0.5f * (stc + mCt24.z - 2.0f * stc * mCt4.z);
        o.w = 0.5f * (sq + tsq4.w - 2.0f * acc.w * (1.0f / K)) +
              0.5f * (stc + mCt24.w - 2.0f * stc * mCt4.w);
        ((float4*)(out + n * T))[lane] = o;
    }
}

extern "C" void kernel_launch(void* const* d_in, const int* in_sizes, int n_in,
                              void* d_out, int out_size) {
    const float* x    = (const float*)d_in[0];
    const int*   edge = (const int*)  d_in[1];   // [2, N*K] int32
    const float* tmpl = (const float*)d_in[2];   // [T, M, M]
    const float* tf   = (const float*)d_in[3];   // [T, M, F]
    float* out = (float*)d_out;

    const int* nbr = edge + N_NODES * K;         // dst row

    precompute_kernel<<<PRE_BLOCKS, PRE_THREADS>>>(x, tmpl, tf);
    ltfwg_kernel<<<N_NODES / NPB, 32 * NPB>>>(nbr, out);
}

// round 17
// speedup vs baseline: 3.8485x; 1.0933x over previous
#include <cuda_runtime.h>

#define N_NODES 50000
#define K 16
#define F 128
#define T 16
#define M 8
#define NPB 8          // nodes per block (one warp each) in main kernel
#define PRE_BLOCKS 512
#define PRE_THREADS 256
#define PRE_WARPS (PRE_BLOCKS * PRE_THREADS / 32)

// Device scratch (no allocation allowed)
__device__ __align__(16) float g_tsq[T];
__device__ __align__(16) float g_mCt[T];
__device__ __align__(16) float g_mCt2[T];
// packed per-node row: [ y[0..15] , z , pad[15] ]  -> 128B, line-aligned
__device__ __align__(128) float g_yz[N_NODES * 32];

// 4-way compare-OR chain + predicated mask-bit set: exactly 5 SASS instr.
template <int BIT>
__device__ __forceinline__ void adj_cmp4(unsigned& mask, const int4& q, int v)
{
    asm("{\n\t.reg .pred p;\n\t"
        "setp.eq.s32 p, %1, %5;\n\t"
        "setp.eq.or.s32 p, %2, %5, p;\n\t"
        "setp.eq.or.s32 p, %3, %5, p;\n\t"
        "setp.eq.or.s32 p, %4, %5, p;\n\t"
        "@p or.b32 %0, %0, %6;\n\t}"
        : "+r"(mask)
        : "r"(q.x), "r"(q.y), "r"(q.z), "r"(q.w),
          "r"(v), "n"(1u << BIT));
}

template <int B>
__device__ __forceinline__ void adj_loop(unsigned& m0, unsigned& m1,
                                         const int4& nnA, const int4& nnB,
                                         const int* nb)
{
    adj_cmp4<B>(m0, nnA, nb[B]);
    adj_cmp4<B>(m1, nnB, nb[B]);
    if constexpr (B + 1 < K) adj_loop<B + 1>(m0, m1, nnA, nnB, nb);
}

// Per-row y/z core: 16 template dots + ||x||^2, butterfly-reduced.
// Returns via the two conditional global stores.
__device__ __forceinline__ void yz_row(const float4& xv, const float4* wv,
                                       int lane, int row)
{
    float a[T];
    #pragma unroll
    for (int t = 0; t < T; t++) {
        float d = xv.x * wv[t].x;
        d = fmaf(xv.y, wv[t].y, d);
        d = fmaf(xv.z, wv[t].z, d);
        d = fmaf(xv.w, wv[t].w, d);
        a[t] = d;
    }
    float s2 = xv.x * xv.x;
    s2 = fmaf(xv.y, xv.y, s2);
    s2 = fmaf(xv.z, xv.z, s2);
    s2 = fmaf(xv.w, xv.w, s2);

    // multi-value butterfly: offsets 16,8,4,2 halve the 16 accs,
    // then offset 1 folds the last lane pair.
    #pragma unroll
    for (int r = 0; r < 4; r++) {
        const int off = 16 >> r;
        const int half = 8 >> r;
        const bool up = (lane & off) != 0;
        #pragma unroll
        for (int i = 0; i < 8; i++) {
            if (i < half) {
                float send = up ? a[i] : a[i + half];
                float got = __shfl_xor_sync(0xffffffffu, send, off);
                a[i] = (up ? a[i + half] : a[i]) + got;
            }
        }
    }
    a[0] += __shfl_xor_sync(0xffffffffu, a[0], 1);

    #pragma unroll
    for (int off = 16; off; off >>= 1)
        s2 += __shfl_xor_sync(0xffffffffu, s2, off);

    // lane L (even) holds t = bit pattern of lane bits 4..1
    const int t = (((lane >> 4) & 1) << 3) | (((lane >> 3) & 1) << 2) |
                  (((lane >> 2) & 1) << 1) | ((lane >> 1) & 1);
    if ((lane & 1) == 0) g_yz[row * 32 + t] = a[0];
    if (lane == 0)       g_yz[row * 32 + 16] = s2;
}

// Fused: per-block tmean (smem, float4 loads) + y/z precompute (2 rows/iter);
// block 0 also emits the per-template scalars.
__global__ __launch_bounds__(PRE_THREADS) void precompute_kernel(
    const float* __restrict__ x, const float* __restrict__ tmpl,
    const float* __restrict__ tf)
{
    __shared__ __align__(16) float s_tmean[T * F];   // 8 KB

    const int tid = threadIdx.x;
    const int w = tid >> 5, lane = tid & 31;

    // block-local tmean via float4: 512 float4-elems, 2 iters per thread.
    // elem i covers (t = i>>5, f4 = i&31): mean over m of tf4[(t*M+m)*32 + f4]
    const float4* tf4 = (const float4*)tf;
    #pragma unroll
    for (int it = 0; it < 2; it++) {
        const int i = tid + it * PRE_THREADS;
        const int t = i >> 5, f4 = i & 31;
        float4 s = make_float4(0.f, 0.f, 0.f, 0.f);
        #pragma unroll
        for (int m = 0; m < M; m++) {
            const float4 v = __ldg(tf4 + (t * M + m) * 32 + f4);
            s.x += v.x; s.y += v.y; s.z += v.z; s.w += v.w;
        }
        ((float4*)s_tmean)[i] = make_float4(s.x * (1.0f / M), s.y * (1.0f / M),
                                            s.z * (1.0f / M), s.w * (1.0f / M));
    }

    // block 0: per-template scalars (warp w covers t = w, w+8)
    if (blockIdx.x == 0) {
        #pragma unroll
        for (int t = w; t < T; t += PRE_THREADS / 32) {
            float s2 = 0.f;
            for (int e = lane; e < M * F; e += 32) {
                const float v = __ldg(tf + t * M * F + e);
                s2 = fmaf(v, v, s2);
            }
            const float v0 = __ldg(tmpl + t * 64 + lane);
            const float v1 = __ldg(tmpl + t * 64 + lane + 32);
            float sa = v0 + v1;
            float sb = v0 * v0 + v1 * v1;
            #pragma unroll
            for (int off = 16; off; off >>= 1) {
                s2 += __shfl_down_sync(0xffffffffu, s2, off);
                sa += __shfl_down_sync(0xffffffffu, sa, off);
                sb += __shfl_down_sync(0xffffffffu, sb, off);
            }
            if (lane == 0) {
                g_tsq[t]  = s2 * (1.0f / M);
                g_mCt[t]  = sa * (1.0f / 64.0f);
                g_mCt2[t] = sb * (1.0f / 64.0f);
            }
        }
    }
    __syncthreads();

    // W slice into registers: lane L holds tmean[t][4L..4L+3] for all 16 t
    float4 wv[T];
    #pragma unroll
    for (int t = 0; t < T; t++)
        wv[t] = ((const float4*)(s_tmean + t * F))[lane];

    const int gw = (blockIdx.x * PRE_THREADS + tid) >> 5;
    int row = gw;
    // paired iterations: two independent rows per trip for shfl-chain ILP
    for (; row + PRE_WARPS < N_NODES; row += 2 * PRE_WARPS) {
        const int rowB = row + PRE_WARPS;
        const float4 xvA = __ldg((const float4*)(x + row  * F) + lane);
        const float4 xvB = __ldg((const float4*)(x + rowB * F) + lane);
        yz_row(xvA, wv, lane, row);
        yz_row(xvB, wv, lane, rowB);
    }
    if (row < N_NODES) {
        const float4 xv = __ldg((const float4*)(x + row * F) + lane);
        yz_row(xv, wv, lane, row);
    }
}

// Main kernel: warp per node, 8 nodes per block. No x access at all.
__global__ __launch_bounds__(32 * NPB) void ltfwg_kernel(
    const int* __restrict__ nbr, float* __restrict__ out)
{
    __shared__ __align__(16) int s_nbrs[NPB][K];

    const int tid = threadIdx.x;
    const int w = tid >> 5, lane = tid & 31;
    const int n = blockIdx.x * NPB + w;

    if (lane < 4)
        ((int4*)s_nbrs[w])[lane] = ((const int4*)(nbr + n * K))[lane];
    __syncwarp();

    // all 16 neighbor ids into registers (broadcast LDS.128)
    int nb[K];
    {
        const int4 q0 = ((const int4*)s_nbrs[w])[0];
        const int4 q1 = ((const int4*)s_nbrs[w])[1];
        const int4 q2 = ((const int4*)s_nbrs[w])[2];
        const int4 q3 = ((const int4*)s_nbrs[w])[3];
        nb[0]=q0.x; nb[1]=q0.y; nb[2]=q0.z; nb[3]=q0.w;
        nb[4]=q1.x; nb[5]=q1.y; nb[6]=q1.z; nb[7]=q1.w;
        nb[8]=q2.x; nb[9]=q2.y; nb[10]=q2.z; nb[11]=q2.w;
        nb[12]=q3.x; nb[13]=q3.y; nb[14]=q3.z; nb[15]=q3.w;
    }

    // neighbors-of-neighbors: 4 lanes per row x int4; rows 0-7 and 8-15
    const int c4 = lane & 3;
    const int rA = s_nbrs[w][lane >> 2];
    const int rB = s_nbrs[w][8 + (lane >> 2)];
    const int4 nnA = __ldg((const int4*)nbr + rA * (K / 4) + c4);
    const int4 nnB = __ldg((const int4*)nbr + rB * (K / 4) + c4);

    // yz gather: 8 lanes per row (sub = lane&7 -> float4 chunk), 4 rows per
    // warp-load, 4 iterations cover 16 neighbors. Each row = exactly 1 line.
    const int sub = lane & 7;
    float4 acc = make_float4(0.f, 0.f, 0.f, 0.f);
    #pragma unroll
    for (int p = 0; p < 4; p++) {
        const int row = s_nbrs[w][p * 4 + (lane >> 3)];
        const float4 v = __ldg((const float4*)(g_yz + row * 32) + sub);
        acc.x += v.x; acc.y += v.y; acc.z += v.z; acc.w += v.w;
    }
    // reduce across the 4 lanes sharing sub (stride 8)
    #pragma unroll
    for (int off = 8; off <= 16; off <<= 1) {
        acc.x += __shfl_xor_sync(0xffffffffu, acc.x, off);
        acc.y += __shfl_xor_sync(0xffffffffu, acc.y, off);
        acc.z += __shfl_xor_sync(0xffffffffu, acc.z, off);
        acc.w += __shfl_xor_sync(0xffffffffu, acc.w, off);
    }
    // lanes 0-3: y sums for t = lane*4..lane*4+3 ; lane 4: z sum in .x
    const float sq = __shfl_sync(0xffffffffu, acc.x, 4) * (1.0f / K);

    // induced adjacency: per-lane 16-bit b-mask via chained setp.eq.or
    // (5 SASS instr per mask update), OR across 4 lanes per row.
    unsigned m0 = 0u, m1 = 0u;
    adj_loop<0>(m0, m1, nnA, nnB, nb);
    m0 |= __shfl_xor_sync(0xffffffffu, m0, 1);
    m0 |= __shfl_xor_sync(0xffffffffu, m0, 2);
    m1 |= __shfl_xor_sync(0xffffffffu, m1, 1);
    m1 |= __shfl_xor_sync(0xffffffffu, m1, 2);
    int cnt = (c4 == 0) ? (__popc(m0 & 0xffffu) + __popc(m1 & 0xffffu)) : 0;
    cnt = __reduce_add_sync(0xffffffffu, cnt);
    const float mC = (float)cnt * (1.0f / (K * K));

    // finalize: lanes 0-3 each produce 4 outputs (float4 store, 64B total)
    if (lane < 4) {
        const float4 tsq4  = __ldg((const float4*)g_tsq  + lane);
        const float4 mCt4  = __ldg((const float4*)g_mCt  + lane);
        const float4 mCt24 = __ldg((const float4*)g_mCt2 + lane);
        const float stc = mC;  // struct term common factor
        float4 o;
        o.x = 0.5f * (sq + tsq4.x - 2.0f * acc.x * (1.0f / K)) +
              0.5f * (stc + mCt24.x - 2.0f * stc * mCt4.x);
        o.y = 0.5f * (sq + tsq4.y - 2.0f * acc.y * (1.0f / K)) +
              0.5f * (stc + mCt24.y - 2.0f * stc * mCt4.y);
        o.z = 0.5f * (sq + tsq4.z - 2.0f * acc.z * (1.0f / K)) +
              0.5f * (stc + mCt24.z - 2.0f * stc * mCt4.z);
        o.w = 0.5f * (sq + tsq4.w - 2.0f * acc.w * (1.0f / K)) +
              0.5f * (stc + mCt24.w - 2.0f * stc * mCt4.w);
        ((float4*)(out + n * T))[lane] = o;
    }
}

extern "C" void kernel_launch(void* const* d_in, const int* in_sizes, int n_in,
                              void* d_out, int out_size) {
    const float* x    = (const float*)d_in[0];
    const int*   edge = (const int*)  d_in[1];   // [2, N*K] int32
    const float* tmpl = (const float*)d_in[2];   // [T, M, M]
    const float* tf   = (const float*)d_in[3];   // [T, M, F]
    float* out = (float*)d_out;

    const int* nbr = edge + N_NODES * K;         // dst row

    precompute_kernel<<<PRE_BLOCKS, PRE_THREADS>>>(x, tmpl, tf);
    ltfwg_kernel<<<N_NODES / NPB, 32 * NPB>>>(nbr, out);
}